// round 6
// baseline (speedup 1.0000x reference)
#include <cuda_runtime.h>
#include <cuda_bf16.h>
#include <cstdint>

// QFNetBlock: normalize -> 4 complex GEMM layers (CNOT perm after 0,2) -> abs.
// Complex GEMM via mma.sync bf16 (hi/lo 3-term split, fp32 accum).
// CTA tile 64x64, 2 CTAs/SM (independent barrier domains overlap), 256 CTAs.

#define DD 4096
#define BB 256
#define NW 12

#define KC 16
#define NCHUNK (DD / KC)   // 256
#define SROW 24            // bf16 per smem row (48 B)
#define SROWB 48

// tile row offsets within one buffer (units: rows of SROW bf16)
#define T_SRH 0
#define T_SRL 64
#define T_SIH 128
#define T_SIL 192
#define T_URH 256
#define T_URL 320
#define T_UIH 384
#define T_UIL 448
#define BUF_ROWS 512
#define BUF_ELEMS (BUF_ROWS * SROW)      // 12288 bf16 = 24576 B
#define SMEM_BYTES (2 * BUF_ELEMS * 2)   // 49152 B

// Ping-pong complex state scratch (4 MB each).
__device__ float g_r0[BB * DD];
__device__ float g_i0[BB * DD];
__device__ float g_r1[BB * DD];
__device__ float g_i1[BB * DD];

__device__ __forceinline__ uint32_t smem_u32(const void* p) {
    uint32_t a;
    asm("{ .reg .u64 t; cvta.to.shared.u64 t, %1; cvt.u32.u64 %0, t; }" : "=r"(a) : "l"(p));
    return a;
}

__device__ __forceinline__ void cvt_hilo2(float a, float b, uint32_t& hi, uint32_t& lo) {
    __nv_bfloat16 ha = __float2bfloat16_rn(a);
    __nv_bfloat16 hb = __float2bfloat16_rn(b);
    __nv_bfloat16 la = __float2bfloat16_rn(a - __bfloat162float(ha));
    __nv_bfloat16 lb = __float2bfloat16_rn(b - __bfloat162float(hb));
    __nv_bfloat162 h2 = __halves2bfloat162(ha, hb);
    __nv_bfloat162 l2 = __halves2bfloat162(la, lb);
    hi = *reinterpret_cast<uint32_t*>(&h2);
    lo = *reinterpret_cast<uint32_t*>(&l2);
}

__device__ __forceinline__ void store_hilo(__nv_bfloat16* bufH, __nv_bfloat16* bufL,
                                           int row, int kp, float4 v) {
    uint32_t h0, l0, h1, l1;
    cvt_hilo2(v.x, v.y, h0, l0);
    cvt_hilo2(v.z, v.w, h1, l1);
    *reinterpret_cast<uint2*>(bufH + row * SROW + kp) = make_uint2(h0, h1);
    *reinterpret_cast<uint2*>(bufL + row * SROW + kp) = make_uint2(l0, l1);
}

__device__ __forceinline__ void ldm4(uint32_t* r, uint32_t addr) {
    asm volatile("ldmatrix.sync.aligned.m8n8.x4.shared.b16 {%0,%1,%2,%3}, [%4];"
                 : "=r"(r[0]), "=r"(r[1]), "=r"(r[2]), "=r"(r[3]) : "r"(addr));
}

#define MMA(C, A, B)                                                           \
    asm volatile(                                                              \
        "mma.sync.aligned.m16n8k16.row.col.f32.bf16.bf16.f32 "                 \
        "{%0,%1,%2,%3}, {%4,%5,%6,%7}, {%8,%9}, {%0,%1,%2,%3};"                \
        : "+f"((C)[0]), "+f"((C)[1]), "+f"((C)[2]), "+f"((C)[3])               \
        : "r"((A)[0]), "r"((A)[1]), "r"((A)[2]), "r"((A)[3]),                  \
          "r"((B)[0]), "r"((B)[1]))

// ---------------------------------------------------------------------------
// Complex GEMM: O[b,i] = sum_k U[i,k] * S[b,k]  (complex, 3-term hi/lo split)
// CTA tile M=64 (batch) x N=64 (i). 8 warps: 4(M) x 2(N), warp tile 16x32.
// grid (DD/64=64, BB/64=4) = 256 CTAs, 256 threads, 2 CTAs/SM.
// ---------------------------------------------------------------------------
template <bool CPLX>
__global__ void __launch_bounds__(256, 2)
cgemm_mma(const float* __restrict__ Ur, const float* __restrict__ Ui,
          const float* __restrict__ Sr, const float* __restrict__ Si,
          float* __restrict__ Or, float* __restrict__ Oi) {
    extern __shared__ __align__(16) __nv_bfloat16 sm[];

    const int tid = threadIdx.x;
    const int wid = tid >> 5;
    const int lane = tid & 31;
    const int ibase = blockIdx.x * 64;
    const int bbase = blockIdx.y * 64;

    // ---- loader mapping: thread -> (tile, row); each stages one full k16 row ----
    const int lrow_ld = tid & 63;
    const int ltile = tid >> 6;  // 0:Sr 1:Si 2:Ur 3:Ui
    const float* lptr;
    int tileH, tileL;
    bool lactive = true;
    switch (ltile) {
        case 0: lptr = Sr + (size_t)(bbase + lrow_ld) * DD; tileH = T_SRH; tileL = T_SRL; break;
        case 1: lptr = Si + (size_t)(bbase + lrow_ld) * DD; tileH = T_SIH; tileL = T_SIL;
                lactive = CPLX; break;
        case 2: lptr = Ur + (size_t)(ibase + lrow_ld) * DD; tileH = T_URH; tileL = T_URL; break;
        default: lptr = Ui + (size_t)(ibase + lrow_ld) * DD; tileH = T_UIH; tileL = T_UIL; break;
    }

    // ---- compute mapping: 4(M) x 2(N) warps, warp tile m16 x n32 ----
    const int warp_m = wid & 3;
    const int warp_n = wid >> 2;
    const int lrow = lane >> 2;
    const int lcol2 = (lane & 3) << 1;

    const uint32_t aLane = (uint32_t)((lane & 15) * SROWB + (lane >> 4) * 16);
    const uint32_t bLane = (uint32_t)((((lane >> 4) << 3) + (lane & 7)) * SROWB +
                                      ((lane >> 3) & 1) * 16);
    const uint32_t smbase = smem_u32(sm);
    const uint32_t aOff = aLane + (uint32_t)(warp_m * 16 * SROWB);

    float cR[4][4], cI[4][4];
#pragma unroll
    for (int n = 0; n < 4; ++n)
#pragma unroll
        for (int r = 0; r < 4; ++r) { cR[n][r] = 0.f; cI[n][r] = 0.f; }

    auto stage = [&](int buf, const float4* v) {
        if (!lactive) return;
        __nv_bfloat16* BH = sm + buf * BUF_ELEMS + tileH * SROW;
        __nv_bfloat16* BL = sm + buf * BUF_ELEMS + tileL * SROW;
#pragma unroll
        for (int j = 0; j < 4; ++j) store_hilo(BH, BL, lrow_ld, j * 4, v[j]);
    };

    // prologue: chunk 0 staged, chunk 1 prefetched
    float4 v[4];
#pragma unroll
    for (int j = 0; j < 4; ++j)
        if (lactive) v[j] = *reinterpret_cast<const float4*>(lptr + j * 4);
    stage(0, v);
#pragma unroll
    for (int j = 0; j < 4; ++j)
        if (lactive) v[j] = *reinterpret_cast<const float4*>(lptr + KC + j * 4);
    __syncthreads();

#pragma unroll 1
    for (int c = 0; c < NCHUNK; ++c) {
        if (c + 1 < NCHUNK) stage((c + 1) & 1, v);
        if (c + 2 < NCHUNK) {
            const int off = (c + 2) * KC;
#pragma unroll
            for (int j = 0; j < 4; ++j)
                if (lactive) v[j] = *reinterpret_cast<const float4*>(lptr + off + j * 4);
        }

        const uint32_t base = smbase + (uint32_t)((c & 1) * BUF_ELEMS * 2);
        uint32_t aSrH[4], aSrL[4], aSiH[4], aSiL[4], aSiHn[4], aSiLn[4];
        ldm4(aSrH, base + aOff + T_SRH * SROWB);
        ldm4(aSrL, base + aOff + T_SRL * SROWB);
        if (CPLX) {
            ldm4(aSiH, base + aOff + T_SIH * SROWB);
            ldm4(aSiL, base + aOff + T_SIL * SROWB);
#pragma unroll
            for (int r = 0; r < 4; ++r) {
                aSiHn[r] = aSiH[r] ^ 0x80008000u;
                aSiLn[r] = aSiL[r] ^ 0x80008000u;
            }
        }
#pragma unroll
        for (int np = 0; np < 2; ++np) {
            const uint32_t bm = base + bLane + (uint32_t)((warp_n * 32 + np * 16) * SROWB);
            uint32_t bUrH[4], bUrL[4], bUiH[4], bUiL[4];
            ldm4(bUrH, bm + T_URH * SROWB);
            ldm4(bUrL, bm + T_URL * SROWB);
            ldm4(bUiH, bm + T_UIH * SROWB);
            ldm4(bUiL, bm + T_UIL * SROWB);
            const int n0 = np * 2, n1 = np * 2 + 1;
            MMA(cR[n0], aSrH, bUrH + 0);
            MMA(cR[n0], aSrL, bUrH + 0);
            MMA(cR[n0], aSrH, bUrL + 0);
            MMA(cR[n1], aSrH, bUrH + 2);
            MMA(cR[n1], aSrL, bUrH + 2);
            MMA(cR[n1], aSrH, bUrL + 2);
            MMA(cI[n0], aSrH, bUiH + 0);
            MMA(cI[n0], aSrL, bUiH + 0);
            MMA(cI[n0], aSrH, bUiL + 0);
            MMA(cI[n1], aSrH, bUiH + 2);
            MMA(cI[n1], aSrL, bUiH + 2);
            MMA(cI[n1], aSrH, bUiL + 2);
            if (CPLX) {
                MMA(cR[n0], aSiHn, bUiH + 0);
                MMA(cR[n0], aSiLn, bUiH + 0);
                MMA(cR[n0], aSiHn, bUiL + 0);
                MMA(cR[n1], aSiHn, bUiH + 2);
                MMA(cR[n1], aSiLn, bUiH + 2);
                MMA(cR[n1], aSiHn, bUiL + 2);
                MMA(cI[n0], aSiH, bUrH + 0);
                MMA(cI[n0], aSiL, bUrH + 0);
                MMA(cI[n0], aSiH, bUrL + 0);
                MMA(cI[n1], aSiH, bUrH + 2);
                MMA(cI[n1], aSiL, bUrH + 2);
                MMA(cI[n1], aSiH, bUrL + 2);
            }
        }
        __syncthreads();
    }

    // epilogue: (B, D) row-major, coalesced float2 per fragment pair
#pragma unroll
    for (int n = 0; n < 4; ++n) {
        const int brow = bbase + warp_m * 16 + lrow;
        const int icol = ibase + warp_n * 32 + n * 8 + lcol2;
        *reinterpret_cast<float2*>(Or + (size_t)brow * DD + icol) =
            make_float2(cR[n][0], cR[n][1]);
        *reinterpret_cast<float2*>(Or + (size_t)(brow + 8) * DD + icol) =
            make_float2(cR[n][2], cR[n][3]);
        *reinterpret_cast<float2*>(Oi + (size_t)brow * DD + icol) =
            make_float2(cI[n][0], cI[n][1]);
        *reinterpret_cast<float2*>(Oi + (size_t)(brow + 8) * DD + icol) =
            make_float2(cI[n][2], cI[n][3]);
    }
}

// ---------------------------------------------------------------------------
__global__ void normalize_kernel(const float* __restrict__ x, float* __restrict__ sr) {
    const int b = blockIdx.x;
    const float4* xv = reinterpret_cast<const float4*>(x + (size_t)b * DD);
    float ss = 0.f;
#pragma unroll 4
    for (int i = threadIdx.x; i < DD / 4; i += blockDim.x) {
        float4 v = xv[i];
        ss += v.x * v.x + v.y * v.y + v.z * v.z + v.w * v.w;
    }
    __shared__ float red[256];
    red[threadIdx.x] = ss;
    __syncthreads();
    for (int s = 128; s > 0; s >>= 1) {
        if (threadIdx.x < s) red[threadIdx.x] += red[threadIdx.x + s];
        __syncthreads();
    }
    const float inv = rsqrtf(red[0]);
    float4* ov = reinterpret_cast<float4*>(sr + (size_t)b * DD);
    for (int i = threadIdx.x; i < DD / 4; i += blockDim.x) {
        float4 v = xv[i];
        v.x *= inv; v.y *= inv; v.z *= inv; v.w *= inv;
        ov[i] = v;
    }
}

__global__ void perm_kernel(const float* __restrict__ inr, const float* __restrict__ ini,
                            float* __restrict__ outr, float* __restrict__ outi) {
    const int idx = blockIdx.x * blockDim.x + threadIdx.x;
    const int b = idx >> 12;
    const int j = idx & (DD - 1);
    int m = j;
#pragma unroll
    for (int i = NW - 1; i >= 0; --i) {
        const int cc = NW - 1 - i;
        const int t = NW - 1 - ((i + 1) % NW);
        m ^= ((m >> cc) & 1) << t;
    }
    const size_t src = ((size_t)b << 12) + m;
    outr[idx] = inr[src];
    outi[idx] = ini[src];
}

__global__ void abs_kernel(const float* __restrict__ re, const float* __restrict__ im,
                           float* __restrict__ out) {
    const int idx = blockIdx.x * blockDim.x + threadIdx.x;
    const float r = re[idx];
    const float i = im[idx];
    out[idx] = sqrtf(r * r + i * i);
}

// ---------------------------------------------------------------------------
extern "C" void kernel_launch(void* const* d_in, const int* in_sizes, int n_in,
                              void* d_out, int out_size) {
    const float* x   = (const float*)d_in[0];
    const float* u0r = (const float*)d_in[1];
    const float* u0i = (const float*)d_in[2];
    const float* u1r = (const float*)d_in[3];
    const float* u1i = (const float*)d_in[4];
    const float* u2r = (const float*)d_in[5];
    const float* u2i = (const float*)d_in[6];
    const float* u3r = (const float*)d_in[7];
    const float* u3i = (const float*)d_in[8];
    float* out = (float*)d_out;

    cudaFuncSetAttribute(cgemm_mma<true>, cudaFuncAttributeMaxDynamicSharedMemorySize,
                         SMEM_BYTES);
    cudaFuncSetAttribute(cgemm_mma<false>, cudaFuncAttributeMaxDynamicSharedMemorySize,
                         SMEM_BYTES);

    float *r0, *i0, *r1, *i1;
    cudaGetSymbolAddress((void**)&r0, g_r0);
    cudaGetSymbolAddress((void**)&i0, g_i0);
    cudaGetSymbolAddress((void**)&r1, g_r1);
    cudaGetSymbolAddress((void**)&i1, g_i1);

    const dim3 gg(DD / 64, BB / 64);  // (64, 4) = 256 CTAs
    const int elems = BB * DD;

    normalize_kernel<<<BB, 256>>>(x, r0);
    cgemm_mma<false><<<gg, 256, SMEM_BYTES>>>(u0r, u0i, r0, r0, r1, i1);
    perm_kernel<<<elems / 256, 256>>>(r1, i1, r0, i0);
    cgemm_mma<true><<<gg, 256, SMEM_BYTES>>>(u1r, u1i, r0, i0, r1, i1);
    cgemm_mma<true><<<gg, 256, SMEM_BYTES>>>(u2r, u2i, r1, i1, r0, i0);
    perm_kernel<<<elems / 256, 256>>>(r0, i0, r1, i1);
    cgemm_mma<true><<<gg, 256, SMEM_BYTES>>>(u3r, u3i, r1, i1, r0, i0);
    abs_kernel<<<elems / 256, 256>>>(r0, i0, out);
}

// round 7
// speedup vs baseline: 1.5929x; 1.5929x over previous
#include <cuda_runtime.h>
#include <cuda_bf16.h>
#include <cstdint>

// QFNetBlock: normalize -> 4 complex GEMM layers (CNOT perm after 0,2) -> abs.
// Complex GEMM via mma.sync bf16 (hi/lo 3-term split, fp32 accum).
// CTA 64x128, warp tile 32x32, double-buffered smem, single barrier/chunk,
// all fragments (A+B) loaded once at iteration top to overlap LDS latency.

#define DD 4096
#define BB 256
#define NW 12

#define KC 16
#define NCHUNK (DD / KC)   // 256
#define SROW 24            // bf16 per smem row (48 B)
#define SROWB 48

// tile row offsets within one buffer (units: rows of SROW bf16)
#define T_SRH 0
#define T_SRL 64
#define T_SIH 128
#define T_SIL 192
#define T_URH 256
#define T_URL 384
#define T_UIH 512
#define T_UIL 640
#define BUF_ROWS 768
#define BUF_ELEMS (BUF_ROWS * SROW)      // 18432 bf16 = 36864 B
#define SMEM_BYTES (2 * BUF_ELEMS * 2)   // 73728 B

// Ping-pong complex state scratch (4 MB each).
__device__ float g_r0[BB * DD];
__device__ float g_i0[BB * DD];
__device__ float g_r1[BB * DD];
__device__ float g_i1[BB * DD];

__device__ __forceinline__ uint32_t smem_u32(const void* p) {
    uint32_t a;
    asm("{ .reg .u64 t; cvta.to.shared.u64 t, %1; cvt.u32.u64 %0, t; }" : "=r"(a) : "l"(p));
    return a;
}

__device__ __forceinline__ void cvt_hilo2(float a, float b, uint32_t& hi, uint32_t& lo) {
    __nv_bfloat16 ha = __float2bfloat16_rn(a);
    __nv_bfloat16 hb = __float2bfloat16_rn(b);
    __nv_bfloat16 la = __float2bfloat16_rn(a - __bfloat162float(ha));
    __nv_bfloat16 lb = __float2bfloat16_rn(b - __bfloat162float(hb));
    __nv_bfloat162 h2 = __halves2bfloat162(ha, hb);
    __nv_bfloat162 l2 = __halves2bfloat162(la, lb);
    hi = *reinterpret_cast<uint32_t*>(&h2);
    lo = *reinterpret_cast<uint32_t*>(&l2);
}

__device__ __forceinline__ void store_hilo(__nv_bfloat16* bufH, __nv_bfloat16* bufL,
                                           int row, int kp, float4 v) {
    uint32_t h0, l0, h1, l1;
    cvt_hilo2(v.x, v.y, h0, l0);
    cvt_hilo2(v.z, v.w, h1, l1);
    *reinterpret_cast<uint2*>(bufH + row * SROW + kp) = make_uint2(h0, h1);
    *reinterpret_cast<uint2*>(bufL + row * SROW + kp) = make_uint2(l0, l1);
}

__device__ __forceinline__ void ldm4(uint32_t* r, uint32_t addr) {
    asm volatile("ldmatrix.sync.aligned.m8n8.x4.shared.b16 {%0,%1,%2,%3}, [%4];"
                 : "=r"(r[0]), "=r"(r[1]), "=r"(r[2]), "=r"(r[3]) : "r"(addr));
}

#define MMA(C, A, B)                                                           \
    asm volatile(                                                              \
        "mma.sync.aligned.m16n8k16.row.col.f32.bf16.bf16.f32 "                 \
        "{%0,%1,%2,%3}, {%4,%5,%6,%7}, {%8,%9}, {%0,%1,%2,%3};"                \
        : "+f"((C)[0]), "+f"((C)[1]), "+f"((C)[2]), "+f"((C)[3])               \
        : "r"((A)[0]), "r"((A)[1]), "r"((A)[2]), "r"((A)[3]),                  \
          "r"((B)[0]), "r"((B)[1]))

// ---------------------------------------------------------------------------
// Complex GEMM: O[b,i] = sum_k U[i,k] * S[b,k]  (complex, 3-term hi/lo split)
// CTA tile M=64 (batch) x N=128 (i). 8 warps: 2(M) x 4(N), warp tile 32x32.
// grid (DD/128=32, BB/64=4) = 128 CTAs, 256 threads.
// ---------------------------------------------------------------------------
template <bool CPLX>
__global__ void __launch_bounds__(256, 1)
cgemm_mma(const float* __restrict__ Ur, const float* __restrict__ Ui,
          const float* __restrict__ Sr, const float* __restrict__ Si,
          float* __restrict__ Or, float* __restrict__ Oi) {
    extern __shared__ __align__(16) __nv_bfloat16 sm[];

    const int tid = threadIdx.x;
    const int wid = tid >> 5;
    const int lane = tid & 31;
    const int ibase = blockIdx.x * 128;
    const int bbase = blockIdx.y * 64;

    // loader mapping: each thread stages 6 float4 (Sr, Si, Ur x2, Ui x2 rows)
    const int arow = tid >> 2;
    const int akp = (tid & 3) << 2;
    const float* pSr = Sr + (size_t)(bbase + arow) * DD + akp;
    const float* pSi = Si + (size_t)(bbase + arow) * DD + akp;
    const float* pUr0 = Ur + (size_t)(ibase + arow) * DD + akp;
    const float* pUr1 = Ur + (size_t)(ibase + arow + 64) * DD + akp;
    const float* pUi0 = Ui + (size_t)(ibase + arow) * DD + akp;
    const float* pUi1 = Ui + (size_t)(ibase + arow + 64) * DD + akp;

    // compute mapping
    const int warp_m = wid & 1;
    const int warp_n = wid >> 1;
    const int lrow = lane >> 2;
    const int lcol2 = (lane & 3) << 1;

    const uint32_t aLane = (uint32_t)((lane & 15) * SROWB + (lane >> 4) * 16);
    const uint32_t bLane = (uint32_t)((((lane >> 4) << 3) + (lane & 7)) * SROWB +
                                      ((lane >> 3) & 1) * 16);
    const uint32_t smbase = smem_u32(sm);

    float cR[2][4][4], cI[2][4][4];
#pragma unroll
    for (int m = 0; m < 2; ++m)
#pragma unroll
        for (int n = 0; n < 4; ++n)
#pragma unroll
            for (int r = 0; r < 4; ++r) { cR[m][n][r] = 0.f; cI[m][n][r] = 0.f; }

    auto stage = [&](int buf, float4 sr, float4 si, float4 ur0, float4 ur1,
                     float4 ui0, float4 ui1) {
        __nv_bfloat16* B = sm + buf * BUF_ELEMS;
        store_hilo(B + T_SRH * SROW, B + T_SRL * SROW, arow, akp, sr);
        if (CPLX)
            store_hilo(B + T_SIH * SROW, B + T_SIL * SROW, arow, akp, si);
        store_hilo(B + T_URH * SROW, B + T_URL * SROW, arow, akp, ur0);
        store_hilo(B + T_URH * SROW, B + T_URL * SROW, arow + 64, akp, ur1);
        store_hilo(B + T_UIH * SROW, B + T_UIL * SROW, arow, akp, ui0);
        store_hilo(B + T_UIH * SROW, B + T_UIL * SROW, arow + 64, akp, ui1);
    };

    // prologue: chunk 0 -> buf 0, prefetch chunk 1 into regs
    float4 v_sr = *reinterpret_cast<const float4*>(pSr);
    float4 v_si = CPLX ? *reinterpret_cast<const float4*>(pSi) : make_float4(0, 0, 0, 0);
    float4 v_ur0 = *reinterpret_cast<const float4*>(pUr0);
    float4 v_ur1 = *reinterpret_cast<const float4*>(pUr1);
    float4 v_ui0 = *reinterpret_cast<const float4*>(pUi0);
    float4 v_ui1 = *reinterpret_cast<const float4*>(pUi1);
    stage(0, v_sr, v_si, v_ur0, v_ur1, v_ui0, v_ui1);
    v_sr = *reinterpret_cast<const float4*>(pSr + KC);
    if (CPLX) v_si = *reinterpret_cast<const float4*>(pSi + KC);
    v_ur0 = *reinterpret_cast<const float4*>(pUr0 + KC);
    v_ur1 = *reinterpret_cast<const float4*>(pUr1 + KC);
    v_ui0 = *reinterpret_cast<const float4*>(pUi0 + KC);
    v_ui1 = *reinterpret_cast<const float4*>(pUi1 + KC);
    __syncthreads();

#pragma unroll 1
    for (int c = 0; c < NCHUNK; ++c) {
        const uint32_t base = smbase + (uint32_t)((c & 1) * BUF_ELEMS * 2);

        // ---- 1) load ALL fragments for chunk c (latency drains during staging) ----
        uint32_t aSrH[2][4], aSrL[2][4], aSiH[2][4], aSiL[2][4];
#pragma unroll
        for (int m = 0; m < 2; ++m) {
            const uint32_t am = base + aLane + (uint32_t)((warp_m * 32 + m * 16) * SROWB);
            ldm4(aSrH[m], am + T_SRH * SROWB);
            ldm4(aSrL[m], am + T_SRL * SROWB);
            if (CPLX) {
                ldm4(aSiH[m], am + T_SIH * SROWB);
                ldm4(aSiL[m], am + T_SIL * SROWB);
            }
        }
        uint32_t bUrH[2][4], bUrL[2][4], bUiH[2][4], bUiL[2][4];
#pragma unroll
        for (int np = 0; np < 2; ++np) {
            const uint32_t bm = base + bLane + (uint32_t)((warp_n * 32 + np * 16) * SROWB);
            ldm4(bUrH[np], bm + T_URH * SROWB);
            ldm4(bUrL[np], bm + T_URL * SROWB);
            ldm4(bUiH[np], bm + T_UIH * SROWB);
            ldm4(bUiL[np], bm + T_UIL * SROWB);
        }

        // ---- 2) stage chunk c+1 (other buffer) + prefetch chunk c+2 ----
        if (c + 1 < NCHUNK)
            stage((c + 1) & 1, v_sr, v_si, v_ur0, v_ur1, v_ui0, v_ui1);
        if (c + 2 < NCHUNK) {
            const int off = (c + 2) * KC;
            v_sr = *reinterpret_cast<const float4*>(pSr + off);
            if (CPLX) v_si = *reinterpret_cast<const float4*>(pSi + off);
            v_ur0 = *reinterpret_cast<const float4*>(pUr0 + off);
            v_ur1 = *reinterpret_cast<const float4*>(pUr1 + off);
            v_ui0 = *reinterpret_cast<const float4*>(pUi0 + off);
            v_ui1 = *reinterpret_cast<const float4*>(pUi1 + off);
        }

        // ---- 3) MMA burst ----
#pragma unroll
        for (int m = 0; m < 2; ++m) {
            uint32_t aSiHn[4], aSiLn[4];
            if (CPLX) {
#pragma unroll
                for (int r = 0; r < 4; ++r) {
                    aSiHn[r] = aSiH[m][r] ^ 0x80008000u;
                    aSiLn[r] = aSiL[m][r] ^ 0x80008000u;
                }
            }
#pragma unroll
            for (int np = 0; np < 2; ++np) {
                const int n0 = np * 2, n1 = np * 2 + 1;
                MMA(cR[m][n0], aSrH[m], bUrH[np] + 0);
                MMA(cR[m][n0], aSrL[m], bUrH[np] + 0);
                MMA(cR[m][n0], aSrH[m], bUrL[np] + 0);
                MMA(cR[m][n1], aSrH[m], bUrH[np] + 2);
                MMA(cR[m][n1], aSrL[m], bUrH[np] + 2);
                MMA(cR[m][n1], aSrH[m], bUrL[np] + 2);
                MMA(cI[m][n0], aSrH[m], bUiH[np] + 0);
                MMA(cI[m][n0], aSrL[m], bUiH[np] + 0);
                MMA(cI[m][n0], aSrH[m], bUiL[np] + 0);
                MMA(cI[m][n1], aSrH[m], bUiH[np] + 2);
                MMA(cI[m][n1], aSrL[m], bUiH[np] + 2);
                MMA(cI[m][n1], aSrH[m], bUiL[np] + 2);
                if (CPLX) {
                    MMA(cR[m][n0], aSiHn, bUiH[np] + 0);
                    MMA(cR[m][n0], aSiLn, bUiH[np] + 0);
                    MMA(cR[m][n0], aSiHn, bUiL[np] + 0);
                    MMA(cR[m][n1], aSiHn, bUiH[np] + 2);
                    MMA(cR[m][n1], aSiLn, bUiH[np] + 2);
                    MMA(cR[m][n1], aSiHn, bUiL[np] + 2);
                    MMA(cI[m][n0], aSiH[m], bUrH[np] + 0);
                    MMA(cI[m][n0], aSiL[m], bUrH[np] + 0);
                    MMA(cI[m][n0], aSiH[m], bUrL[np] + 0);
                    MMA(cI[m][n1], aSiH[m], bUrH[np] + 2);
                    MMA(cI[m][n1], aSiL[m], bUrH[np] + 2);
                    MMA(cI[m][n1], aSiH[m], bUrL[np] + 2);
                }
            }
        }
        __syncthreads();
    }

    // epilogue: (B, D) row-major, coalesced float2 per fragment pair
#pragma unroll
    for (int m = 0; m < 2; ++m) {
#pragma unroll
        for (int n = 0; n < 4; ++n) {
            const int brow = bbase + warp_m * 32 + m * 16 + lrow;
            const int icol = ibase + warp_n * 32 + n * 8 + lcol2;
            *reinterpret_cast<float2*>(Or + (size_t)brow * DD + icol) =
                make_float2(cR[m][n][0], cR[m][n][1]);
            *reinterpret_cast<float2*>(Or + (size_t)(brow + 8) * DD + icol) =
                make_float2(cR[m][n][2], cR[m][n][3]);
            *reinterpret_cast<float2*>(Oi + (size_t)brow * DD + icol) =
                make_float2(cI[m][n][0], cI[m][n][1]);
            *reinterpret_cast<float2*>(Oi + (size_t)(brow + 8) * DD + icol) =
                make_float2(cI[m][n][2], cI[m][n][3]);
        }
    }
}

// ---------------------------------------------------------------------------
__global__ void normalize_kernel(const float* __restrict__ x, float* __restrict__ sr) {
    const int b = blockIdx.x;
    const float4* xv = reinterpret_cast<const float4*>(x + (size_t)b * DD);
    float ss = 0.f;
#pragma unroll 4
    for (int i = threadIdx.x; i < DD / 4; i += blockDim.x) {
        float4 v = xv[i];
        ss += v.x * v.x + v.y * v.y + v.z * v.z + v.w * v.w;
    }
    __shared__ float red[256];
    red[threadIdx.x] = ss;
    __syncthreads();
    for (int s = 128; s > 0; s >>= 1) {
        if (threadIdx.x < s) red[threadIdx.x] += red[threadIdx.x + s];
        __syncthreads();
    }
    const float inv = rsqrtf(red[0]);
    float4* ov = reinterpret_cast<float4*>(sr + (size_t)b * DD);
    for (int i = threadIdx.x; i < DD / 4; i += blockDim.x) {
        float4 v = xv[i];
        v.x *= inv; v.y *= inv; v.z *= inv; v.w *= inv;
        ov[i] = v;
    }
}

__global__ void perm_kernel(const float* __restrict__ inr, const float* __restrict__ ini,
                            float* __restrict__ outr, float* __restrict__ outi) {
    const int idx = blockIdx.x * blockDim.x + threadIdx.x;
    const int b = idx >> 12;
    const int j = idx & (DD - 1);
    int m = j;
#pragma unroll
    for (int i = NW - 1; i >= 0; --i) {
        const int cc = NW - 1 - i;
        const int t = NW - 1 - ((i + 1) % NW);
        m ^= ((m >> cc) & 1) << t;
    }
    const size_t src = ((size_t)b << 12) + m;
    outr[idx] = inr[src];
    outi[idx] = ini[src];
}

__global__ void abs_kernel(const float* __restrict__ re, const float* __restrict__ im,
                           float* __restrict__ out) {
    const int idx = blockIdx.x * blockDim.x + threadIdx.x;
    const float r = re[idx];
    const float i = im[idx];
    out[idx] = sqrtf(r * r + i * i);
}

// ---------------------------------------------------------------------------
extern "C" void kernel_launch(void* const* d_in, const int* in_sizes, int n_in,
                              void* d_out, int out_size) {
    const float* x   = (const float*)d_in[0];
    const float* u0r = (const float*)d_in[1];
    const float* u0i = (const float*)d_in[2];
    const float* u1r = (const float*)d_in[3];
    const float* u1i = (const float*)d_in[4];
    const float* u2r = (const float*)d_in[5];
    const float* u2i = (const float*)d_in[6];
    const float* u3r = (const float*)d_in[7];
    const float* u3i = (const float*)d_in[8];
    float* out = (float*)d_out;

    cudaFuncSetAttribute(cgemm_mma<true>, cudaFuncAttributeMaxDynamicSharedMemorySize,
                         SMEM_BYTES);
    cudaFuncSetAttribute(cgemm_mma<false>, cudaFuncAttributeMaxDynamicSharedMemorySize,
                         SMEM_BYTES);

    float *r0, *i0, *r1, *i1;
    cudaGetSymbolAddress((void**)&r0, g_r0);
    cudaGetSymbolAddress((void**)&i0, g_i0);
    cudaGetSymbolAddress((void**)&r1, g_r1);
    cudaGetSymbolAddress((void**)&i1, g_i1);

    const dim3 gg(DD / 128, BB / 64);  // (32, 4) = 128 CTAs
    const int elems = BB * DD;

    normalize_kernel<<<BB, 256>>>(x, r0);
    cgemm_mma<false><<<gg, 256, SMEM_BYTES>>>(u0r, u0i, r0, r0, r1, i1);
    perm_kernel<<<elems / 256, 256>>>(r1, i1, r0, i0);
    cgemm_mma<true><<<gg, 256, SMEM_BYTES>>>(u1r, u1i, r0, i0, r1, i1);
    cgemm_mma<true><<<gg, 256, SMEM_BYTES>>>(u2r, u2i, r1, i1, r0, i0);
    perm_kernel<<<elems / 256, 256>>>(r0, i0, r1, i1);
    cgemm_mma<true><<<gg, 256, SMEM_BYTES>>>(u3r, u3i, r1, i1, r0, i0);
    abs_kernel<<<elems / 256, 256>>>(r0, i0, out);
}

// round 8
// speedup vs baseline: 1.6381x; 1.0284x over previous
#include <cuda_runtime.h>
#include <cuda_bf16.h>
#include <cstdint>

// QFNetBlock: normalize -> 4 complex GEMM layers (CNOT perm after 0,2) -> abs.
// Complex GEMM via mma.sync bf16 (hi/lo 3-term split, fp32 accum).
// CTA 64x64, 128 threads (4 warps, 2x2, warp tile 32x32), 2 CTAs/SM for
// cross-CTA latency hiding; double-buffered smem; hoisted fragment loads.

#define DD 4096
#define BB 256
#define NW 12

#define KC 16
#define NCHUNK (DD / KC)   // 256
#define SROW 24            // bf16 per smem row (48 B)
#define SROWB 48

// tile row offsets within one buffer (units: rows of SROW bf16)
#define T_SRH 0
#define T_SRL 64
#define T_SIH 128
#define T_SIL 192
#define T_URH 256
#define T_URL 320
#define T_UIH 384
#define T_UIL 448
#define BUF_ROWS 512
#define BUF_ELEMS (BUF_ROWS * SROW)      // 12288 bf16 = 24576 B
#define SMEM_BYTES (2 * BUF_ELEMS * 2)   // 49152 B

// Ping-pong complex state scratch (4 MB each).
__device__ float g_r0[BB * DD];
__device__ float g_i0[BB * DD];
__device__ float g_r1[BB * DD];
__device__ float g_i1[BB * DD];

__device__ __forceinline__ uint32_t smem_u32(const void* p) {
    uint32_t a;
    asm("{ .reg .u64 t; cvta.to.shared.u64 t, %1; cvt.u32.u64 %0, t; }" : "=r"(a) : "l"(p));
    return a;
}

__device__ __forceinline__ void cvt_hilo2(float a, float b, uint32_t& hi, uint32_t& lo) {
    __nv_bfloat16 ha = __float2bfloat16_rn(a);
    __nv_bfloat16 hb = __float2bfloat16_rn(b);
    __nv_bfloat16 la = __float2bfloat16_rn(a - __bfloat162float(ha));
    __nv_bfloat16 lb = __float2bfloat16_rn(b - __bfloat162float(hb));
    __nv_bfloat162 h2 = __halves2bfloat162(ha, hb);
    __nv_bfloat162 l2 = __halves2bfloat162(la, lb);
    hi = *reinterpret_cast<uint32_t*>(&h2);
    lo = *reinterpret_cast<uint32_t*>(&l2);
}

__device__ __forceinline__ void store_hilo(__nv_bfloat16* bufH, __nv_bfloat16* bufL,
                                           int row, int kp, float4 v) {
    uint32_t h0, l0, h1, l1;
    cvt_hilo2(v.x, v.y, h0, l0);
    cvt_hilo2(v.z, v.w, h1, l1);
    *reinterpret_cast<uint2*>(bufH + row * SROW + kp) = make_uint2(h0, h1);
    *reinterpret_cast<uint2*>(bufL + row * SROW + kp) = make_uint2(l0, l1);
}

__device__ __forceinline__ void ldm4(uint32_t* r, uint32_t addr) {
    asm volatile("ldmatrix.sync.aligned.m8n8.x4.shared.b16 {%0,%1,%2,%3}, [%4];"
                 : "=r"(r[0]), "=r"(r[1]), "=r"(r[2]), "=r"(r[3]) : "r"(addr));
}

#define MMA(C, A, B)                                                           \
    asm volatile(                                                              \
        "mma.sync.aligned.m16n8k16.row.col.f32.bf16.bf16.f32 "                 \
        "{%0,%1,%2,%3}, {%4,%5,%6,%7}, {%8,%9}, {%0,%1,%2,%3};"                \
        : "+f"((C)[0]), "+f"((C)[1]), "+f"((C)[2]), "+f"((C)[3])               \
        : "r"((A)[0]), "r"((A)[1]), "r"((A)[2]), "r"((A)[3]),                  \
          "r"((B)[0]), "r"((B)[1]))

// ---------------------------------------------------------------------------
// Complex GEMM: O[b,i] = sum_k U[i,k] * S[b,k]  (complex, 3-term hi/lo split)
// CTA tile M=64 (batch) x N=64 (i). 4 warps: 2(M) x 2(N), warp tile 32x32.
// grid (DD/64=64, BB/64=4) = 256 CTAs, 128 threads, 2 CTAs/SM.
// ---------------------------------------------------------------------------
template <bool CPLX>
__global__ void __launch_bounds__(128, 2)
cgemm_mma(const float* __restrict__ Ur, const float* __restrict__ Ui,
          const float* __restrict__ Sr, const float* __restrict__ Si,
          float* __restrict__ Or, float* __restrict__ Oi) {
    extern __shared__ __align__(16) __nv_bfloat16 sm[];

    const int tid = threadIdx.x;
    const int wid = tid >> 5;
    const int lane = tid & 31;
    const int ibase = blockIdx.x * 64;
    const int bbase = blockIdx.y * 64;

    // loader mapping: 128 threads; each stages rows r and r+32 of all 4 tiles
    const int arow = tid >> 2;            // 0..31
    const int akp = (tid & 3) << 2;       // 0,4,8,12
    const float* pSr0 = Sr + (size_t)(bbase + arow) * DD + akp;
    const float* pSr1 = Sr + (size_t)(bbase + arow + 32) * DD + akp;
    const float* pSi0 = Si + (size_t)(bbase + arow) * DD + akp;
    const float* pSi1 = Si + (size_t)(bbase + arow + 32) * DD + akp;
    const float* pUr0 = Ur + (size_t)(ibase + arow) * DD + akp;
    const float* pUr1 = Ur + (size_t)(ibase + arow + 32) * DD + akp;
    const float* pUi0 = Ui + (size_t)(ibase + arow) * DD + akp;
    const float* pUi1 = Ui + (size_t)(ibase + arow + 32) * DD + akp;

    // compute mapping: 2(M) x 2(N) warps, warp tile 32x32
    const int warp_m = wid & 1;
    const int warp_n = wid >> 1;
    const int lrow = lane >> 2;
    const int lcol2 = (lane & 3) << 1;

    const uint32_t aLane = (uint32_t)((lane & 15) * SROWB + (lane >> 4) * 16);
    const uint32_t bLane = (uint32_t)((((lane >> 4) << 3) + (lane & 7)) * SROWB +
                                      ((lane >> 3) & 1) * 16);
    const uint32_t smbase = smem_u32(sm);

    float cR[2][4][4], cI[2][4][4];
#pragma unroll
    for (int m = 0; m < 2; ++m)
#pragma unroll
        for (int n = 0; n < 4; ++n)
#pragma unroll
            for (int r = 0; r < 4; ++r) { cR[m][n][r] = 0.f; cI[m][n][r] = 0.f; }

    auto stage = [&](int buf, const float4* v) {
        __nv_bfloat16* B = sm + buf * BUF_ELEMS;
        store_hilo(B + T_SRH * SROW, B + T_SRL * SROW, arow, akp, v[0]);
        store_hilo(B + T_SRH * SROW, B + T_SRL * SROW, arow + 32, akp, v[1]);
        if (CPLX) {
            store_hilo(B + T_SIH * SROW, B + T_SIL * SROW, arow, akp, v[2]);
            store_hilo(B + T_SIH * SROW, B + T_SIL * SROW, arow + 32, akp, v[3]);
        }
        store_hilo(B + T_URH * SROW, B + T_URL * SROW, arow, akp, v[4]);
        store_hilo(B + T_URH * SROW, B + T_URL * SROW, arow + 32, akp, v[5]);
        store_hilo(B + T_UIH * SROW, B + T_UIL * SROW, arow, akp, v[6]);
        store_hilo(B + T_UIH * SROW, B + T_UIL * SROW, arow + 32, akp, v[7]);
    };
    auto prefetch = [&](float4* v, int off) {
        v[0] = *reinterpret_cast<const float4*>(pSr0 + off);
        v[1] = *reinterpret_cast<const float4*>(pSr1 + off);
        if (CPLX) {
            v[2] = *reinterpret_cast<const float4*>(pSi0 + off);
            v[3] = *reinterpret_cast<const float4*>(pSi1 + off);
        }
        v[4] = *reinterpret_cast<const float4*>(pUr0 + off);
        v[5] = *reinterpret_cast<const float4*>(pUr1 + off);
        v[6] = *reinterpret_cast<const float4*>(pUi0 + off);
        v[7] = *reinterpret_cast<const float4*>(pUi1 + off);
    };

    // prologue: chunk 0 -> buf 0, prefetch chunk 1 into regs
    float4 v[8];
    prefetch(v, 0);
    stage(0, v);
    prefetch(v, KC);
    __syncthreads();

#pragma unroll 1
    for (int c = 0; c < NCHUNK; ++c) {
        const uint32_t base = smbase + (uint32_t)((c & 1) * BUF_ELEMS * 2);

        // ---- 1) load ALL fragments for chunk c ----
        uint32_t aSrH[2][4], aSrL[2][4], aSiH[2][4], aSiL[2][4];
#pragma unroll
        for (int m = 0; m < 2; ++m) {
            const uint32_t am = base + aLane + (uint32_t)((warp_m * 32 + m * 16) * SROWB);
            ldm4(aSrH[m], am + T_SRH * SROWB);
            ldm4(aSrL[m], am + T_SRL * SROWB);
            if (CPLX) {
                ldm4(aSiH[m], am + T_SIH * SROWB);
                ldm4(aSiL[m], am + T_SIL * SROWB);
            }
        }
        uint32_t bUrH[2][4], bUrL[2][4], bUiH[2][4], bUiL[2][4];
#pragma unroll
        for (int np = 0; np < 2; ++np) {
            const uint32_t bm = base + bLane + (uint32_t)((warp_n * 32 + np * 16) * SROWB);
            ldm4(bUrH[np], bm + T_URH * SROWB);
            ldm4(bUrL[np], bm + T_URL * SROWB);
            ldm4(bUiH[np], bm + T_UIH * SROWB);
            ldm4(bUiL[np], bm + T_UIL * SROWB);
        }

        // ---- 2) stage chunk c+1 + prefetch chunk c+2 ----
        if (c + 1 < NCHUNK) stage((c + 1) & 1, v);
        if (c + 2 < NCHUNK) prefetch(v, (c + 2) * KC);

        // ---- 3) MMA burst ----
#pragma unroll
        for (int m = 0; m < 2; ++m) {
            uint32_t aSiHn[4], aSiLn[4];
            if (CPLX) {
#pragma unroll
                for (int r = 0; r < 4; ++r) {
                    aSiHn[r] = aSiH[m][r] ^ 0x80008000u;
                    aSiLn[r] = aSiL[m][r] ^ 0x80008000u;
                }
            }
#pragma unroll
            for (int np = 0; np < 2; ++np) {
                const int n0 = np * 2, n1 = np * 2 + 1;
                MMA(cR[m][n0], aSrH[m], bUrH[np] + 0);
                MMA(cR[m][n0], aSrL[m], bUrH[np] + 0);
                MMA(cR[m][n0], aSrH[m], bUrL[np] + 0);
                MMA(cR[m][n1], aSrH[m], bUrH[np] + 2);
                MMA(cR[m][n1], aSrL[m], bUrH[np] + 2);
                MMA(cR[m][n1], aSrH[m], bUrL[np] + 2);
                MMA(cI[m][n0], aSrH[m], bUiH[np] + 0);
                MMA(cI[m][n0], aSrL[m], bUiH[np] + 0);
                MMA(cI[m][n0], aSrH[m], bUiL[np] + 0);
                MMA(cI[m][n1], aSrH[m], bUiH[np] + 2);
                MMA(cI[m][n1], aSrL[m], bUiH[np] + 2);
                MMA(cI[m][n1], aSrH[m], bUiL[np] + 2);
                if (CPLX) {
                    MMA(cR[m][n0], aSiHn, bUiH[np] + 0);
                    MMA(cR[m][n0], aSiLn, bUiH[np] + 0);
                    MMA(cR[m][n0], aSiHn, bUiL[np] + 0);
                    MMA(cR[m][n1], aSiHn, bUiH[np] + 2);
                    MMA(cR[m][n1], aSiLn, bUiH[np] + 2);
                    MMA(cR[m][n1], aSiHn, bUiL[np] + 2);
                    MMA(cI[m][n0], aSiH[m], bUrH[np] + 0);
                    MMA(cI[m][n0], aSiL[m], bUrH[np] + 0);
                    MMA(cI[m][n0], aSiH[m], bUrL[np] + 0);
                    MMA(cI[m][n1], aSiH[m], bUrH[np] + 2);
                    MMA(cI[m][n1], aSiL[m], bUrH[np] + 2);
                    MMA(cI[m][n1], aSiH[m], bUrL[np] + 2);
                }
            }
        }
        __syncthreads();
    }

    // epilogue: (B, D) row-major, coalesced float2 per fragment pair
#pragma unroll
    for (int m = 0; m < 2; ++m) {
#pragma unroll
        for (int n = 0; n < 4; ++n) {
            const int brow = bbase + warp_m * 32 + m * 16 + lrow;
            const int icol = ibase + warp_n * 32 + n * 8 + lcol2;
            *reinterpret_cast<float2*>(Or + (size_t)brow * DD + icol) =
                make_float2(cR[m][n][0], cR[m][n][1]);
            *reinterpret_cast<float2*>(Or + (size_t)(brow + 8) * DD + icol) =
                make_float2(cR[m][n][2], cR[m][n][3]);
            *reinterpret_cast<float2*>(Oi + (size_t)brow * DD + icol) =
                make_float2(cI[m][n][0], cI[m][n][1]);
            *reinterpret_cast<float2*>(Oi + (size_t)(brow + 8) * DD + icol) =
                make_float2(cI[m][n][2], cI[m][n][3]);
        }
    }
}

// ---------------------------------------------------------------------------
__global__ void normalize_kernel(const float* __restrict__ x, float* __restrict__ sr) {
    const int b = blockIdx.x;
    const float4* xv = reinterpret_cast<const float4*>(x + (size_t)b * DD);
    float ss = 0.f;
#pragma unroll 4
    for (int i = threadIdx.x; i < DD / 4; i += blockDim.x) {
        float4 v = xv[i];
        ss += v.x * v.x + v.y * v.y + v.z * v.z + v.w * v.w;
    }
    __shared__ float red[256];
    red[threadIdx.x] = ss;
    __syncthreads();
    for (int s = 128; s > 0; s >>= 1) {
        if (threadIdx.x < s) red[threadIdx.x] += red[threadIdx.x + s];
        __syncthreads();
    }
    const float inv = rsqrtf(red[0]);
    float4* ov = reinterpret_cast<float4*>(sr + (size_t)b * DD);
    for (int i = threadIdx.x; i < DD / 4; i += blockDim.x) {
        float4 v = xv[i];
        v.x *= inv; v.y *= inv; v.z *= inv; v.w *= inv;
        ov[i] = v;
    }
}

__global__ void perm_kernel(const float* __restrict__ inr, const float* __restrict__ ini,
                            float* __restrict__ outr, float* __restrict__ outi) {
    const int idx = blockIdx.x * blockDim.x + threadIdx.x;
    const int b = idx >> 12;
    const int j = idx & (DD - 1);
    int m = j;
#pragma unroll
    for (int i = NW - 1; i >= 0; --i) {
        const int cc = NW - 1 - i;
        const int t = NW - 1 - ((i + 1) % NW);
        m ^= ((m >> cc) & 1) << t;
    }
    const size_t src = ((size_t)b << 12) + m;
    outr[idx] = inr[src];
    outi[idx] = ini[src];
}

__global__ void abs_kernel(const float* __restrict__ re, const float* __restrict__ im,
                           float* __restrict__ out) {
    const int idx = blockIdx.x * blockDim.x + threadIdx.x;
    const float r = re[idx];
    const float i = im[idx];
    out[idx] = sqrtf(r * r + i * i);
}

// ---------------------------------------------------------------------------
extern "C" void kernel_launch(void* const* d_in, const int* in_sizes, int n_in,
                              void* d_out, int out_size) {
    const float* x   = (const float*)d_in[0];
    const float* u0r = (const float*)d_in[1];
    const float* u0i = (const float*)d_in[2];
    const float* u1r = (const float*)d_in[3];
    const float* u1i = (const float*)d_in[4];
    const float* u2r = (const float*)d_in[5];
    const float* u2i = (const float*)d_in[6];
    const float* u3r = (const float*)d_in[7];
    const float* u3i = (const float*)d_in[8];
    float* out = (float*)d_out;

    cudaFuncSetAttribute(cgemm_mma<true>, cudaFuncAttributeMaxDynamicSharedMemorySize,
                         SMEM_BYTES);
    cudaFuncSetAttribute(cgemm_mma<false>, cudaFuncAttributeMaxDynamicSharedMemorySize,
                         SMEM_BYTES);

    float *r0, *i0, *r1, *i1;
    cudaGetSymbolAddress((void**)&r0, g_r0);
    cudaGetSymbolAddress((void**)&i0, g_i0);
    cudaGetSymbolAddress((void**)&r1, g_r1);
    cudaGetSymbolAddress((void**)&i1, g_i1);

    const dim3 gg(DD / 64, BB / 64);  // (64, 4) = 256 CTAs
    const int elems = BB * DD;

    normalize_kernel<<<BB, 256>>>(x, r0);
    cgemm_mma<false><<<gg, 128, SMEM_BYTES>>>(u0r, u0i, r0, r0, r1, i1);
    perm_kernel<<<elems / 256, 256>>>(r1, i1, r0, i0);
    cgemm_mma<true><<<gg, 128, SMEM_BYTES>>>(u1r, u1i, r0, i0, r1, i1);
    cgemm_mma<true><<<gg, 128, SMEM_BYTES>>>(u2r, u2i, r1, i1, r0, i0);
    perm_kernel<<<elems / 256, 256>>>(r0, i0, r1, i1);
    cgemm_mma<true><<<gg, 128, SMEM_BYTES>>>(u3r, u3i, r1, i1, r0, i0);
    abs_kernel<<<elems / 256, 256>>>(r0, i0, out);
}